// round 6
// baseline (speedup 1.0000x reference)
#include <cuda_runtime.h>

// HSTU positional encoder, cp.async multi-stage pipelined version.
// out[i,:] = x[i,:]*sqrt(D) + pos_weight[pos_ind(i),:] + ts_weight[ts_ind(i),:]
// D = 512 fp32 (2 KB/row), L = 32768, B = 16, P = 8192, NTB = 2048.

#define D 512
#define ALPHA 22.627416997969522f   // sqrt(512)
#define MAX_POS 8192
#define NTB 2048
#define TIME_BUCKET_INCREMENTS 60.0f

#define ROWS   16                   // rows per CTA
#define STAGES 6                    // pipeline depth (6 KB/stage)

__device__ __forceinline__ unsigned smem_u32(const void* p) {
    unsigned a;
    asm("{ .reg .u64 t; cvta.to.shared.u64 t, %1; cvt.u32.u64 %0, t; }"
        : "=r"(a) : "l"(p));
    return a;
}

__device__ __forceinline__ void cp_async16(void* dst, const void* src) {
    asm volatile("cp.async.cg.shared.global [%0], [%1], 16;"
                 :: "r"(smem_u32(dst)), "l"(src) : "memory");
}
__device__ __forceinline__ void cp_commit() {
    asm volatile("cp.async.commit_group;" ::: "memory");
}
template <int N>
__device__ __forceinline__ void cp_wait() {
    asm volatile("cp.async.wait_group %0;" :: "n"(N) : "memory");
}

__global__ __launch_bounds__(128)
void hstu_pos_enc_pipe(
    const int* __restrict__ seq_lengths,   // [B]
    const int* __restrict__ seq_offsets,   // [B+1]
    const float* __restrict__ x,           // [L, D]
    const int* __restrict__ num_targets,   // [B]
    const int* __restrict__ seq_ts,        // [L]
    const float* __restrict__ pos_weight,  // [P, D]
    const float* __restrict__ ts_weight,   // [NTB+1, D]
    float* __restrict__ out,               // [L, D]
    int B, int L)
{
    __shared__ __align__(16) float s_x[STAGES][D];
    __shared__ __align__(16) float s_p[STAGES][D];
    __shared__ __align__(16) float s_t[STAGES][D];
    __shared__ int s_pos[ROWS];
    __shared__ int s_ts[ROWS];

    const int tid  = threadIdx.x;
    const int base = blockIdx.x * ROWS;

    int n_rows = L - base;
    if (n_rows > ROWS) n_rows = ROWS;
    if (n_rows < 0)    n_rows = 0;

    // ---- index precompute: thread r handles row base+r ----
    if (tid < n_rows) {
        const int row = base + tid;

        int lo = 0, hi = B - 1;
        while (lo < hi) {
            int mid = (lo + hi + 1) >> 1;
            if (seq_offsets[mid] <= row) lo = mid; else hi = mid - 1;
        }
        const int b = lo;

        const int off = seq_offsets[b];
        const int rel_pos = row - off;

        int len = seq_lengths[b]; if (len < 0) len = 0;
        int nt  = num_targets[b]; if (nt  < 0) nt  = 0;
        int high_ind = len - nt;  if (high_ind < 0) high_ind = 0;

        int p = (rel_pos < high_ind) ? rel_pos : high_ind;
        p = high_ind - p;                   // MAX_CONTEXTUAL_SEQ_LEN = 0
        if (p > MAX_POS - 1) p = MAX_POS - 1;
        if (p < 0) p = 0;
        s_pos[tid] = p;

        const int end = seq_offsets[b + 1];
        const float qt = (float)seq_ts[end - 1];
        const float tt = (float)seq_ts[row];
        float dt = qt - tt;                 // TIME_DELTA = 0
        if (dt < 1e-6f) dt = 1e-6f;
        dt = dt / TIME_BUCKET_INCREMENTS;
        const float v = sqrtf(dt);          // TIME_BUCKET_SCALE = 1
        int ti = (int)v;
        if (ti > NTB) ti = NTB;
        s_ts[tid] = ti;
    }
    __syncthreads();

    const int c = tid * 4;   // float offset of this thread's 16B slice

    // ---- prologue: fill STAGES-1 stages ----
    #pragma unroll
    for (int j = 0; j < STAGES - 1; j++) {
        if (j < n_rows) {
            const int s = j;
            cp_async16(&s_x[s][c], x          + (size_t)(base + j) * D + c);
            cp_async16(&s_p[s][c], pos_weight + (size_t)s_pos[j]   * D + c);
            cp_async16(&s_t[s][c], ts_weight  + (size_t)s_ts[j]    * D + c);
        }
        cp_commit();
    }

    // ---- steady state ----
    int stage = 0;
    int wstage = (STAGES - 1) % STAGES;
    for (int i = 0; i < n_rows; i++) {
        const int j = i + STAGES - 1;
        if (j < n_rows) {
            cp_async16(&s_x[wstage][c], x          + (size_t)(base + j) * D + c);
            cp_async16(&s_p[wstage][c], pos_weight + (size_t)s_pos[j]   * D + c);
            cp_async16(&s_t[wstage][c], ts_weight  + (size_t)s_ts[j]    * D + c);
        }
        cp_commit();
        cp_wait<STAGES - 2>();      // guarantees group for row i is complete
        __syncthreads();

        const float4 xv = *(const float4*)&s_x[stage][c];
        const float4 pv = *(const float4*)&s_p[stage][c];
        const float4 tv = *(const float4*)&s_t[stage][c];
        float4 ov;
        ov.x = fmaf(xv.x, ALPHA, pv.x + tv.x);
        ov.y = fmaf(xv.y, ALPHA, pv.y + tv.y);
        ov.z = fmaf(xv.z, ALPHA, pv.z + tv.z);
        ov.w = fmaf(xv.w, ALPHA, pv.w + tv.w);
        __stcs((float4*)(out + (size_t)(base + i) * D) + tid, ov);

        __syncthreads();            // protect stage buffer before reuse next iter

        if (++stage == STAGES)  stage = 0;
        if (++wstage == STAGES) wstage = 0;
    }
}

extern "C" void kernel_launch(void* const* d_in, const int* in_sizes, int n_in,
                              void* d_out, int out_size)
{
    // Input order (metadata): [max_seq_len?], seq_lengths, seq_offsets,
    // seq_embeddings, num_targets, seq_timestamps, pos_weight, ts_weight.
    int o = (n_in == 8) ? 1 : 0;

    const int*   seq_lengths = (const int*)  d_in[o + 0];
    const int*   seq_offsets = (const int*)  d_in[o + 1];
    const float* x           = (const float*)d_in[o + 2];
    const int*   num_targets = (const int*)  d_in[o + 3];
    const int*   seq_ts      = (const int*)  d_in[o + 4];
    const float* pos_weight  = (const float*)d_in[o + 5];
    const float* ts_weight   = (const float*)d_in[o + 6];
    float*       out         = (float*)d_out;

    const int B = in_sizes[o + 0];          // seq_lengths element count
    const int L = out_size / D;             // total token rows

    const int grid = (L + ROWS - 1) / ROWS;
    hstu_pos_enc_pipe<<<grid, 128>>>(seq_lengths, seq_offsets, x, num_targets,
                                     seq_ts, pos_weight, ts_weight, out, B, L);
}